// round 6
// baseline (speedup 1.0000x reference)
#include <cuda_runtime.h>
#include <cuda_bf16.h>

// FineMatching (P=512, R=S=128, K=3, THRESH=0.05, OR-combine, conditional scale).
// R6: two-kernel split.
//   A: per-proposal top-3 thresholds on RAW x (exp is monotone) -> 512KB scratch.
//      Tile in smem, no exp, no stores of the dense maps.
//   B: dense streaming pass. No tile, ~2KB smem, 4 CTAs/SM, grid 512 = ONE wave.
//      Reads x (L2-resident after A), e=__expf(x), compares raw thresholds,
//      streaming-writes score+corr.

#define PP 512
#define NT 512
#define THRESH 0.05f

__device__ float g_thr[PP * 256];   // [p][0..127]=rowTx, [p][128..255]=colTx

struct Top3 { float v1, v2, v3; };

__device__ __forceinline__ void ins3(Top3& t, float v) {
    float t1 = fminf(t.v1, v);
    float t2 = fminf(t.v2, v);
    t.v1 = fmaxf(t.v1, v);
    t.v2 = fmaxf(t.v2, t1);
    t.v3 = fmaxf(t.v3, t2);
}

__device__ __forceinline__ void merge(Top3& a, const Top3& b) {
    ins3(a, b.v1);
    ins3(a, b.v2);
    ins3(a, b.v3);
}

__device__ __forceinline__ void merge_xor1(Top3& t) {
    Top3 b;
    b.v1 = __shfl_xor_sync(0xffffffffu, t.v1, 1);
    b.v2 = __shfl_xor_sync(0xffffffffu, t.v2, 1);
    b.v3 = __shfl_xor_sync(0xffffffffu, t.v3, 1);
    merge(t, b);
}

#define T3INIT {-1e30f, -1e30f, -1e30f}

// ---------------- Kernel A: thresholds on raw x ----------------
__global__ __launch_bounds__(NT, 3) void thresh_kernel(
    const float4* __restrict__ msm4)
{
    extern __shared__ float4 sh4[];          // tile [128 rows x 33 f4], pitch 132 fl
    float* e = (float*)sh4;

    const int p    = blockIdx.x;
    const int tid  = threadIdx.x;
    const int lane = tid & 31;

    // P1: pure load + STS (no exp). 2-deep prefetch.
    {
        const float4* g = msm4 + p * 4096 + tid;
        float4* sp = sh4 + (tid >> 5) * 33 + lane;
        float4 cur = g[0];
        #pragma unroll
        for (int k = 0; k < 8; k++) {
            float4 nxt;
            if (k < 7) nxt = g[(k + 1) * NT];
            sp[k * 16 * 33] = cur;
            cur = nxt;
        }
    }
    __syncthreads();

    // P2: top-3 scans (4 interleaved accumulators), leaders STG raw thresholds.
    if (tid < 256) {
        // columns: 2 threads/col; half1 rows 68..127 then 64..67 (+16-bank stagger)
        const int s    = tid >> 1;
        const int half = tid & 1;
        Top3 t0 = T3INIT, t1 = T3INIT, t2 = T3INIT, t3 = T3INIT;
        const float* pa = e + (half ? 68 * 132 : 0) + s;
        #pragma unroll
        for (int j = 0; j < 15; j++) {
            ins3(t0, pa[(4 * j + 0) * 132]);
            ins3(t1, pa[(4 * j + 1) * 132]);
            ins3(t2, pa[(4 * j + 2) * 132]);
            ins3(t3, pa[(4 * j + 3) * 132]);
        }
        const float* pb = e + (half ? 64 * 132 : 60 * 132) + s;
        ins3(t0, pb[0 * 132]);
        ins3(t1, pb[1 * 132]);
        ins3(t2, pb[2 * 132]);
        ins3(t3, pb[3 * 132]);
        merge(t0, t1);
        merge(t2, t3);
        merge(t0, t2);
        merge_xor1(t0);
        if (!half) g_thr[p * 256 + 128 + s] = t0.v3;    // colTx
    } else {
        // rows: 2 threads/row via LDS.128; half1 f4 20..31 then 16..19
        const int u    = tid - 256;
        const int r    = u >> 1;
        const int half = u & 1;
        Top3 t0 = T3INIT, t1 = T3INIT, t2 = T3INIT, t3 = T3INIT;
        const float4* ra = sh4 + r * 33 + (half ? 20 : 0);
        #pragma unroll
        for (int j = 0; j < 12; j++) {
            float4 v = ra[j];
            ins3(t0, v.x);
            ins3(t1, v.y);
            ins3(t2, v.z);
            ins3(t3, v.w);
        }
        const float4* rb = sh4 + r * 33 + (half ? 16 : 12);
        #pragma unroll
        for (int j = 0; j < 4; j++) {
            float4 v = rb[j];
            ins3(t0, v.x);
            ins3(t1, v.y);
            ins3(t2, v.z);
            ins3(t3, v.w);
        }
        merge(t0, t1);
        merge(t2, t3);
        merge(t0, t2);
        merge_xor1(t0);
        if (!half) g_thr[p * 256 + r] = t0.v3;          // rowTx
    }
}

// ---------------- Kernel B: dense streaming output ----------------
__global__ __launch_bounds__(NT, 4) void output_kernel(
    const float4* __restrict__ msm4,
    const unsigned int* __restrict__ refm,
    const unsigned int* __restrict__ srcm,
    const float* __restrict__ ncs,
    float4* __restrict__ out4,
    int write_corr)
{
    __shared__ float2 rowInfo[128];   // (rowTx, refmaskF)
    __shared__ float  colTx[128];
    __shared__ float  smF[128];

    const int p    = blockIdx.x;
    const int tid  = threadIdx.x;
    const int lane = tid & 31;

    if (tid < 128) {
        rowInfo[tid] = make_float2(g_thr[p * 256 + tid],
                                   (refm[p * 128 + tid] != 0u) ? 1.0f : 0.0f);
        colTx[tid] = g_thr[p * 256 + 128 + tid];
        smF[tid]   = (srcm[p * 128 + tid] != 0u) ? 1.0f : 0.0f;
    }
    __syncthreads();

    const float scale = 0.5f * __ldg(ncs + p);
    const float4 cT = *(const float4*)(colTx + 4 * lane);
    const float4 m4 = *(const float4*)(smF + 4 * lane);

    const float4* g   = msm4 + p * 4096 + tid;
    const float2* rip = rowInfo + (tid >> 5);
    float4* sco = out4 + (size_t)p * 4096 + tid;
    float4* cor = sco + (size_t)PP * 4096;

    if (write_corr) {
        #pragma unroll
        for (int k = 0; k < 8; k++) {
            float4 x  = g[k * NT];
            float2 ri = rip[16 * k];            // warp-uniform (rowTx, refmaskF)

            float ex = __expf(x.x), ey = __expf(x.y);
            float ez = __expf(x.z), ew = __expf(x.w);

            bool ax = x.x >= ri.x, bx = x.x >= cT.x;
            bool ay = x.y >= ri.x, by = x.y >= cT.y;
            bool az = x.z >= ri.x, bz = x.z >= cT.z;
            bool aw = x.w >= ri.x, bw = x.w >= cT.w;

            float svx = scale * ex, svy = scale * ey;
            float svz = scale * ez, svw = scale * ew;

            float4 s4;
            s4.x = (ax ? svx : 0.f) + (bx ? svx : 0.f);
            s4.y = (ay ? svy : 0.f) + (by ? svy : 0.f);
            s4.z = (az ? svz : 0.f) + (bz ? svz : 0.f);
            s4.w = (aw ? svw : 0.f) + (bw ? svw : 0.f);
            __stcs(sco + k * NT, s4);

            float4 c4;
            c4.x = ((ax || bx) && ex > THRESH) ? ri.y * m4.x : 0.f;
            c4.y = ((ay || by) && ey > THRESH) ? ri.y * m4.y : 0.f;
            c4.z = ((az || bz) && ez > THRESH) ? ri.y * m4.z : 0.f;
            c4.w = ((aw || bw) && ew > THRESH) ? ri.y * m4.w : 0.f;
            __stcs(cor + k * NT, c4);
        }
    } else {
        #pragma unroll
        for (int k = 0; k < 8; k++) {
            float4 x  = g[k * NT];
            float2 ri = rip[16 * k];
            float ex = __expf(x.x), ey = __expf(x.y);
            float ez = __expf(x.z), ew = __expf(x.w);
            bool ax = x.x >= ri.x, bx = x.x >= cT.x;
            bool ay = x.y >= ri.x, by = x.y >= cT.y;
            bool az = x.z >= ri.x, bz = x.z >= cT.z;
            bool aw = x.w >= ri.x, bw = x.w >= cT.w;
            float svx = scale * ex, svy = scale * ey;
            float svz = scale * ez, svw = scale * ew;
            float4 s4;
            s4.x = (ax ? svx : 0.f) + (bx ? svx : 0.f);
            s4.y = (ay ? svy : 0.f) + (by ? svy : 0.f);
            s4.z = (az ? svz : 0.f) + (bz ? svz : 0.f);
            s4.w = (aw ? svw : 0.f) + (bw ? svw : 0.f);
            __stcs(sco + k * NT, s4);
        }
    }
}

extern "C" void kernel_launch(void* const* d_in, const int* in_sizes, int n_in,
                              void* d_out, int out_size) {
    const float4* msm4       = (const float4*)d_in[0];
    const unsigned int* refm = (const unsigned int*)d_in[1];
    const unsigned int* srcm = (const unsigned int*)d_in[2];
    const float* ncs         = (const float*)d_in[3];
    float4* out4             = (float4*)d_out;

    const int prs = PP * 128 * 128;
    int write_corr = (out_size >= 2 * prs) ? 1 : 0;

    size_t smemA = (size_t)(128 * 132) * sizeof(float);   // 67.6KB
    cudaFuncSetAttribute(thresh_kernel,
                         cudaFuncAttributeMaxDynamicSharedMemorySize, (int)smemA);

    thresh_kernel<<<PP, NT, smemA>>>(msm4);
    output_kernel<<<PP, NT>>>(msm4, refm, srcm, ncs, out4, write_corr);
}

// round 7
// speedup vs baseline: 1.0917x; 1.0917x over previous
#include <cuda_runtime.h>
#include <cuda_bf16.h>

// FineMatching (P=512, R=S=128, K=3, THRESH=0.05, OR-combine, conditional scale).
//   rowT[r]/colT[s] = 3rd-largest raw x of row/col (exp monotone -> same argmax)
//   e = exp(x); score = 0.5*ncs[p]*e*((x>=rowTx)+(x>=colTx))
//   corr = ((x>=rowTx)|(x>=colTx)) & (e>0.05) & refm[r] & srcm[s]
//
// R7: monolith, L2-residency oriented.
//  - PLAIN stores (no .cs): out (67MB) + msm (33.5MB) = 100.6MB < 126MB L2;
//    in steady-state graph replay outputs stay L2-resident -> DRAM writes ~0.
//  - Tile holds RAW x: P1 = pure LDG/STS (no MUFU in latency phase);
//    P3 computes __expf from smem where it overlaps store issue.
//  - P2: 4 interleaved top-3 accumulators; halves bank-staggered (+16 banks).
// Smem pitch 132 floats; all phases bank-conflict-free.

#define PP 512
#define NT 512
#define THRESH 0.05f

struct Top3 { float v1, v2, v3; };

__device__ __forceinline__ void ins3(Top3& t, float v) {
    float t1 = fminf(t.v1, v);
    float t2 = fminf(t.v2, v);
    t.v1 = fmaxf(t.v1, v);
    t.v2 = fmaxf(t.v2, t1);
    t.v3 = fmaxf(t.v3, t2);
}

__device__ __forceinline__ void merge(Top3& a, const Top3& b) {
    ins3(a, b.v1);
    ins3(a, b.v2);
    ins3(a, b.v3);
}

__device__ __forceinline__ void merge_xor1(Top3& t) {
    Top3 b;
    b.v1 = __shfl_xor_sync(0xffffffffu, t.v1, 1);
    b.v2 = __shfl_xor_sync(0xffffffffu, t.v2, 1);
    b.v3 = __shfl_xor_sync(0xffffffffu, t.v3, 1);
    merge(t, b);
}

#define T3INIT {-1e30f, -1e30f, -1e30f}

__global__ __launch_bounds__(NT, 3) void fine_matching_kernel(
    const float4* __restrict__ msm4,        // [P,R,S] as float4 (raw log-scores)
    const unsigned int* __restrict__ refm,  // [P,R] 32-bit bool
    const uint4* __restrict__ srcm4,        // [P,S] 32-bit bool as uint4
    const float* __restrict__ ncs,          // [P]
    float4* __restrict__ out4,              // [score | corr] as float4
    int write_corr)
{
    extern __shared__ float4 sh4[];
    float* e        = (float*)sh4;                  // [128*132] raw x
    float2* rowInfo = (float2*)(e + 128 * 132);     // [128] (rowTx, refmaskF)
    float* colTx    = (float*)(rowInfo + 128);      // [128]

    const int p    = blockIdx.x;
    const int tid  = threadIdx.x;
    const int lane = tid & 31;

    // ---- Phase 0/1: ref-mask; raw-x tile load (pure LDG.128/STS.128, 2-deep)
    if (tid < 128) rowInfo[tid].y = (refm[p * 128 + tid] != 0u) ? 1.0f : 0.0f;

    {
        const float4* g = msm4 + p * 4096 + tid;
        float4* sp = sh4 + (tid >> 5) * 33 + lane;
        float4 cur = g[0];
        #pragma unroll
        for (int k = 0; k < 8; k++) {
            float4 nxt;
            if (k < 7) nxt = g[(k + 1) * NT];
            sp[k * 16 * 33] = cur;
            cur = nxt;
        }
    }
    __syncthreads();

    // ---- Phase 2: raw-x top-3 thresholds, 4 interleaved accumulators
    if (tid < 256) {
        // columns: 2 threads/col; half1 rows 68..127 then 64..67 (+16 banks)
        const int s    = tid >> 1;
        const int half = tid & 1;
        Top3 t0 = T3INIT, t1 = T3INIT, t2 = T3INIT, t3 = T3INIT;
        const float* pa = e + (half ? 68 * 132 : 0) + s;
        #pragma unroll
        for (int j = 0; j < 15; j++) {
            ins3(t0, pa[(4 * j + 0) * 132]);
            ins3(t1, pa[(4 * j + 1) * 132]);
            ins3(t2, pa[(4 * j + 2) * 132]);
            ins3(t3, pa[(4 * j + 3) * 132]);
        }
        const float* pb = e + (half ? 64 * 132 : 60 * 132) + s;
        ins3(t0, pb[0 * 132]);
        ins3(t1, pb[1 * 132]);
        ins3(t2, pb[2 * 132]);
        ins3(t3, pb[3 * 132]);
        merge(t0, t1);
        merge(t2, t3);
        merge(t0, t2);
        merge_xor1(t0);
        if (!half) colTx[s] = t0.v3;
    } else {
        // rows: 2 threads/row via LDS.128; half1 f4 20..31 then 16..19
        const int u    = tid - 256;
        const int r    = u >> 1;
        const int half = u & 1;
        Top3 t0 = T3INIT, t1 = T3INIT, t2 = T3INIT, t3 = T3INIT;
        const float4* ra = sh4 + r * 33 + (half ? 20 : 0);
        #pragma unroll
        for (int j = 0; j < 12; j++) {
            float4 v = ra[j];
            ins3(t0, v.x);
            ins3(t1, v.y);
            ins3(t2, v.z);
            ins3(t3, v.w);
        }
        const float4* rb = sh4 + r * 33 + (half ? 16 : 12);
        #pragma unroll
        for (int j = 0; j < 4; j++) {
            float4 v = rb[j];
            ins3(t0, v.x);
            ins3(t1, v.y);
            ins3(t2, v.z);
            ins3(t3, v.w);
        }
        merge(t0, t1);
        merge(t2, t3);
        merge(t0, t2);
        merge_xor1(t0);
        if (!half) rowInfo[r].x = t0.v3;
    }
    __syncthreads();

    // ---- Phase 3: dense output. exp from smem raw x; PLAIN stores (L2-resident)
    const float scale = 0.5f * __ldg(ncs + p);
    const float4 cT = *(const float4*)(colTx + 4 * lane);
    const uint4 smv = srcm4[p * 32 + lane];
    const float m0 = (smv.x != 0u) ? 1.f : 0.f;
    const float m1 = (smv.y != 0u) ? 1.f : 0.f;
    const float m2 = (smv.z != 0u) ? 1.f : 0.f;
    const float m3 = (smv.w != 0u) ? 1.f : 0.f;

    const float4* tp  = sh4 + (tid >> 5) * 33 + lane;
    const float2* rip = rowInfo + (tid >> 5);
    float4* sco = out4 + (size_t)p * 4096 + tid;
    float4* cor = sco + (size_t)PP * 4096;

    if (write_corr) {
        #pragma unroll
        for (int k = 0; k < 8; k++) {
            float2 ri = rip[16 * k];            // warp-uniform (rowTx, refmaskF)
            float4 x  = tp[k * 16 * 33];

            float ex = __expf(x.x), ey = __expf(x.y);
            float ez = __expf(x.z), ew = __expf(x.w);

            bool ax = x.x >= ri.x, bx = x.x >= cT.x;
            bool ay = x.y >= ri.x, by = x.y >= cT.y;
            bool az = x.z >= ri.x, bz = x.z >= cT.z;
            bool aw = x.w >= ri.x, bw = x.w >= cT.w;

            float svx = scale * ex, svy = scale * ey;
            float svz = scale * ez, svw = scale * ew;

            float4 s4;
            s4.x = (ax ? svx : 0.f) + (bx ? svx : 0.f);
            s4.y = (ay ? svy : 0.f) + (by ? svy : 0.f);
            s4.z = (az ? svz : 0.f) + (bz ? svz : 0.f);
            s4.w = (aw ? svw : 0.f) + (bw ? svw : 0.f);
            sco[k * NT] = s4;

            float4 c4;
            c4.x = ((ax || bx) && ex > THRESH) ? ri.y * m0 : 0.f;
            c4.y = ((ay || by) && ey > THRESH) ? ri.y * m1 : 0.f;
            c4.z = ((az || bz) && ez > THRESH) ? ri.y * m2 : 0.f;
            c4.w = ((aw || bw) && ew > THRESH) ? ri.y * m3 : 0.f;
            cor[k * NT] = c4;
        }
    } else {
        #pragma unroll
        for (int k = 0; k < 8; k++) {
            float2 ri = rip[16 * k];
            float4 x  = tp[k * 16 * 33];
            float ex = __expf(x.x), ey = __expf(x.y);
            float ez = __expf(x.z), ew = __expf(x.w);
            bool ax = x.x >= ri.x, bx = x.x >= cT.x;
            bool ay = x.y >= ri.x, by = x.y >= cT.y;
            bool az = x.z >= ri.x, bz = x.z >= cT.z;
            bool aw = x.w >= ri.x, bw = x.w >= cT.w;
            float svx = scale * ex, svy = scale * ey;
            float svz = scale * ez, svw = scale * ew;
            float4 s4;
            s4.x = (ax ? svx : 0.f) + (bx ? svx : 0.f);
            s4.y = (ay ? svy : 0.f) + (by ? svy : 0.f);
            s4.z = (az ? svz : 0.f) + (bz ? svz : 0.f);
            s4.w = (aw ? svw : 0.f) + (bw ? svw : 0.f);
            sco[k * NT] = s4;
        }
    }
}

extern "C" void kernel_launch(void* const* d_in, const int* in_sizes, int n_in,
                              void* d_out, int out_size) {
    const float4* msm4       = (const float4*)d_in[0];
    const unsigned int* refm = (const unsigned int*)d_in[1];
    const uint4* srcm4       = (const uint4*)d_in[2];
    const float* ncs         = (const float*)d_in[3];
    float4* out4             = (float4*)d_out;

    const int prs = PP * 128 * 128;
    int write_corr = (out_size >= 2 * prs) ? 1 : 0;

    size_t smem = (size_t)(128 * 132) * sizeof(float)
                + 128 * sizeof(float2) + 128 * sizeof(float);   // ~69KB
    cudaFuncSetAttribute(fine_matching_kernel,
                         cudaFuncAttributeMaxDynamicSharedMemorySize, (int)smem);

    fine_matching_kernel<<<PP, NT, smem>>>(msm4, refm, srcm4, ncs, out4,
                                           write_corr);
}

// round 8
// speedup vs baseline: 1.2111x; 1.1094x over previous
#include <cuda_runtime.h>
#include <cuda_bf16.h>

// FineMatching (P=512, R=S=128, K=3, THRESH=0.05, OR-combine, conditional scale).
//   rowTx[r]/colTx[s] = 3rd-largest raw x of row/col (exp monotone)
//   score = 0.5*ncs[p]*exp(x)*((x>=rowTx)+(x>=colTx))
//   corr  = ((x>=rowTx)|(x>=colTx)) & (x>ln(0.05)) & refm[r] & srcm[s]
//
// R8: load-latency attack. P1 uses cp.async.cg (LDGSTS): 8 in-flight 16B
// copies per thread, global->smem direct, no data registers -> MLP 8 at
// unchanged occupancy (3 CTAs/SM, regs ~40). One latency exposure per CTA
// instead of ~4. P2 = 4-accumulator raw-x scans (R5). P3 = __stcs streaming
// stores (R4-proven), exp only for the score value, x-domain threshold.
// Smem pitch 132 floats; all phases bank-conflict-free.

#define PP 512
#define NT 512
#define XTHRESH (-2.99573227355f)   // ln(0.05)

struct Top3 { float v1, v2, v3; };

__device__ __forceinline__ void ins3(Top3& t, float v) {
    float t1 = fminf(t.v1, v);
    float t2 = fminf(t.v2, v);
    t.v1 = fmaxf(t.v1, v);
    t.v2 = fmaxf(t.v2, t1);
    t.v3 = fmaxf(t.v3, t2);
}

__device__ __forceinline__ void merge(Top3& a, const Top3& b) {
    ins3(a, b.v1);
    ins3(a, b.v2);
    ins3(a, b.v3);
}

__device__ __forceinline__ void merge_xor1(Top3& t) {
    Top3 b;
    b.v1 = __shfl_xor_sync(0xffffffffu, t.v1, 1);
    b.v2 = __shfl_xor_sync(0xffffffffu, t.v2, 1);
    b.v3 = __shfl_xor_sync(0xffffffffu, t.v3, 1);
    merge(t, b);
}

#define T3INIT {-1e30f, -1e30f, -1e30f}

__global__ __launch_bounds__(NT, 3) void fine_matching_kernel(
    const float4* __restrict__ msm4,        // [P,R,S] as float4 (raw log-scores)
    const unsigned int* __restrict__ refm,  // [P,R] 32-bit bool
    const uint4* __restrict__ srcm4,        // [P,S] 32-bit bool as uint4
    const float* __restrict__ ncs,          // [P]
    float4* __restrict__ out4,              // [score | corr] as float4
    int write_corr)
{
    extern __shared__ float4 sh4[];
    float* e        = (float*)sh4;                  // [128*132] raw x
    float2* rowInfo = (float2*)(e + 128 * 132);     // [128] (rowTx, refmaskF)
    float* colTx    = (float*)(rowInfo + 128);      // [128]

    const int p    = blockIdx.x;
    const int tid  = threadIdx.x;
    const int lane = tid & 31;

    // ---- Phase 0/1: ref-mask; tile fill via cp.async.cg (8 in flight, MLP 8)
    if (tid < 128) rowInfo[tid].y = (refm[p * 128 + tid] != 0u) ? 1.0f : 0.0f;

    {
        const float4* g = msm4 + p * 4096 + tid;
        unsigned int sp = (unsigned int)__cvta_generic_to_shared(
            sh4 + (tid >> 5) * 33 + lane);
        #pragma unroll
        for (int k = 0; k < 8; k++) {
            asm volatile("cp.async.cg.shared.global [%0], [%1], 16;"
                         :: "r"(sp + k * (16 * 33 * 16)), "l"(g + k * NT));
        }
        asm volatile("cp.async.commit_group;");
        asm volatile("cp.async.wait_group 0;" ::: "memory");
    }
    __syncthreads();

    // ---- Phase 2: raw-x top-3 thresholds, 4 interleaved accumulators
    if (tid < 256) {
        // columns: 2 threads/col; half1 rows 68..127 then 64..67 (+16 banks)
        const int s    = tid >> 1;
        const int half = tid & 1;
        Top3 t0 = T3INIT, t1 = T3INIT, t2 = T3INIT, t3 = T3INIT;
        const float* pa = e + (half ? 68 * 132 : 0) + s;
        #pragma unroll
        for (int j = 0; j < 15; j++) {
            ins3(t0, pa[(4 * j + 0) * 132]);
            ins3(t1, pa[(4 * j + 1) * 132]);
            ins3(t2, pa[(4 * j + 2) * 132]);
            ins3(t3, pa[(4 * j + 3) * 132]);
        }
        const float* pb = e + (half ? 64 * 132 : 60 * 132) + s;
        ins3(t0, pb[0 * 132]);
        ins3(t1, pb[1 * 132]);
        ins3(t2, pb[2 * 132]);
        ins3(t3, pb[3 * 132]);
        merge(t0, t1);
        merge(t2, t3);
        merge(t0, t2);
        merge_xor1(t0);
        if (!half) colTx[s] = t0.v3;
    } else {
        // rows: 2 threads/row via LDS.128; half1 f4 20..31 then 16..19
        const int u    = tid - 256;
        const int r    = u >> 1;
        const int half = u & 1;
        Top3 t0 = T3INIT, t1 = T3INIT, t2 = T3INIT, t3 = T3INIT;
        const float4* ra = sh4 + r * 33 + (half ? 20 : 0);
        #pragma unroll
        for (int j = 0; j < 12; j++) {
            float4 v = ra[j];
            ins3(t0, v.x);
            ins3(t1, v.y);
            ins3(t2, v.z);
            ins3(t3, v.w);
        }
        const float4* rb = sh4 + r * 33 + (half ? 16 : 12);
        #pragma unroll
        for (int j = 0; j < 4; j++) {
            float4 v = rb[j];
            ins3(t0, v.x);
            ins3(t1, v.y);
            ins3(t2, v.z);
            ins3(t3, v.w);
        }
        merge(t0, t1);
        merge(t2, t3);
        merge(t0, t2);
        merge_xor1(t0);
        if (!half) rowInfo[r].x = t0.v3;
    }
    __syncthreads();

    // ---- Phase 3: dense output; exp only for score; __stcs streaming stores
    const float scale = 0.5f * __ldg(ncs + p);
    const float4 cT = *(const float4*)(colTx + 4 * lane);
    const uint4 smv = srcm4[p * 32 + lane];
    const float m0 = (smv.x != 0u) ? 1.f : 0.f;
    const float m1 = (smv.y != 0u) ? 1.f : 0.f;
    const float m2 = (smv.z != 0u) ? 1.f : 0.f;
    const float m3 = (smv.w != 0u) ? 1.f : 0.f;

    const float4* tp  = sh4 + (tid >> 5) * 33 + lane;
    const float2* rip = rowInfo + (tid >> 5);
    float4* sco = out4 + (size_t)p * 4096 + tid;
    float4* cor = sco + (size_t)PP * 4096;

    if (write_corr) {
        #pragma unroll
        for (int k = 0; k < 8; k++) {
            float2 ri = rip[16 * k];            // warp-uniform (rowTx, refmaskF)
            float4 x  = tp[k * 16 * 33];

            bool ax = x.x >= ri.x, bx = x.x >= cT.x;
            bool ay = x.y >= ri.x, by = x.y >= cT.y;
            bool az = x.z >= ri.x, bz = x.z >= cT.z;
            bool aw = x.w >= ri.x, bw = x.w >= cT.w;

            float svx = scale * __expf(x.x), svy = scale * __expf(x.y);
            float svz = scale * __expf(x.z), svw = scale * __expf(x.w);

            float4 s4;
            s4.x = (ax ? svx : 0.f) + (bx ? svx : 0.f);
            s4.y = (ay ? svy : 0.f) + (by ? svy : 0.f);
            s4.z = (az ? svz : 0.f) + (bz ? svz : 0.f);
            s4.w = (aw ? svw : 0.f) + (bw ? svw : 0.f);
            __stcs(sco + k * NT, s4);

            float4 c4;
            c4.x = ((ax || bx) && x.x > XTHRESH) ? ri.y * m0 : 0.f;
            c4.y = ((ay || by) && x.y > XTHRESH) ? ri.y * m1 : 0.f;
            c4.z = ((az || bz) && x.z > XTHRESH) ? ri.y * m2 : 0.f;
            c4.w = ((aw || bw) && x.w > XTHRESH) ? ri.y * m3 : 0.f;
            __stcs(cor + k * NT, c4);
        }
    } else {
        #pragma unroll
        for (int k = 0; k < 8; k++) {
            float2 ri = rip[16 * k];
            float4 x  = tp[k * 16 * 33];
            bool ax = x.x >= ri.x, bx = x.x >= cT.x;
            bool ay = x.y >= ri.x, by = x.y >= cT.y;
            bool az = x.z >= ri.x, bz = x.z >= cT.z;
            bool aw = x.w >= ri.x, bw = x.w >= cT.w;
            float svx = scale * __expf(x.x), svy = scale * __expf(x.y);
            float svz = scale * __expf(x.z), svw = scale * __expf(x.w);
            float4 s4;
            s4.x = (ax ? svx : 0.f) + (bx ? svx : 0.f);
            s4.y = (ay ? svy : 0.f) + (by ? svy : 0.f);
            s4.z = (az ? svz : 0.f) + (bz ? svz : 0.f);
            s4.w = (aw ? svw : 0.f) + (bw ? svw : 0.f);
            __stcs(sco + k * NT, s4);
        }
    }
}

extern "C" void kernel_launch(void* const* d_in, const int* in_sizes, int n_in,
                              void* d_out, int out_size) {
    const float4* msm4       = (const float4*)d_in[0];
    const unsigned int* refm = (const unsigned int*)d_in[1];
    const uint4* srcm4       = (const uint4*)d_in[2];
    const float* ncs         = (const float*)d_in[3];
    float4* out4             = (float4*)d_out;

    const int prs = PP * 128 * 128;
    int write_corr = (out_size >= 2 * prs) ? 1 : 0;

    size_t smem = (size_t)(128 * 132) * sizeof(float)
                + 128 * sizeof(float2) + 128 * sizeof(float);   // ~69KB
    cudaFuncSetAttribute(fine_matching_kernel,
                         cudaFuncAttributeMaxDynamicSharedMemorySize, (int)smem);

    fine_matching_kernel<<<PP, NT, smem>>>(msm4, refm, srcm4, ncs, out4,
                                           write_corr);
}

// round 9
// speedup vs baseline: 1.3210x; 1.0908x over previous
#include <cuda_runtime.h>
#include <cuda_bf16.h>
#include <cstdint>

// FineMatching (P=512, R=S=128, K=3, THRESH=0.05, OR-combine, conditional).
// R9: 2-CTA clusters, one half-proposal (64 rows x 128 cols) per CTA.
//   grid 1024 x 256 thr, ~37KB smem -> 6 CTAs/SM; tail granule halved.
//   Rows: local top-3. Cols: 64-row partial top-3, exchanged with cluster
//   peer via DSMEM (mapa + ld.shared::cluster), merged locally.
//   Thresholds on raw x (exp monotone); score uses __expf; __stcs stores.

#define PP 512
#define NT 256
#define XTHRESH (-2.99573227355f)   // ln(0.05)

struct Top3 { float v1, v2, v3; };

__device__ __forceinline__ void ins3(Top3& t, float v) {
    float t1 = fminf(t.v1, v);
    float t2 = fminf(t.v2, v);
    t.v1 = fmaxf(t.v1, v);
    t.v2 = fmaxf(t.v2, t1);
    t.v3 = fmaxf(t.v3, t2);
}

__device__ __forceinline__ void merge(Top3& a, const Top3& b) {
    ins3(a, b.v1);
    ins3(a, b.v2);
    ins3(a, b.v3);
}

__device__ __forceinline__ void merge_xor1(Top3& t) {
    Top3 b;
    b.v1 = __shfl_xor_sync(0xffffffffu, t.v1, 1);
    b.v2 = __shfl_xor_sync(0xffffffffu, t.v2, 1);
    b.v3 = __shfl_xor_sync(0xffffffffu, t.v3, 1);
    merge(t, b);
}

#define T3INIT {-1e30f, -1e30f, -1e30f}

__device__ __forceinline__ float ld_peer_f32(uint32_t local_saddr, uint32_t peer_rank) {
    uint32_t ra;
    float v;
    asm volatile("mapa.shared::cluster.u32 %0, %1, %2;"
                 : "=r"(ra) : "r"(local_saddr), "r"(peer_rank));
    asm volatile("ld.shared::cluster.f32 %0, [%1];" : "=f"(v) : "r"(ra));
    return v;
}

__global__ __launch_bounds__(NT, 6) __cluster_dims__(2, 1, 1)
void fine_matching_kernel(
    const float4* __restrict__ msm4,        // [P,R,S] as float4 (raw log-scores)
    const unsigned int* __restrict__ refm,  // [P,R] 32-bit bool
    const uint4* __restrict__ srcm4,        // [P,S] 32-bit bool as uint4
    const float* __restrict__ ncs,          // [P]
    float4* __restrict__ out4,              // [score | corr] as float4
    int write_corr)
{
    __shared__ __align__(16) float tile[64 * 132];   // half-tile, pitch 132
    __shared__ float cp1[128], cp2[128], cp3[128];   // my col partial top-3
    __shared__ __align__(16) float colT[128];        // merged col thresholds
    __shared__ float2 rowInfo[64];                   // (rowTx, refmaskF)

    const int bid  = blockIdx.x;
    const int p    = bid >> 1;
    const int half = bid & 1;                        // == cluster rank
    const uint32_t peer = (uint32_t)(half ^ 1);
    const int tid  = threadIdx.x;
    const int lane = tid & 31;

    // ---- P0/P1: masks; half-tile fill via cp.async (8 x 16B in flight)
    if (tid < 64)
        rowInfo[tid].y = (refm[p * 128 + half * 64 + tid] != 0u) ? 1.0f : 0.0f;

    {
        const float4* g = msm4 + p * 4096 + half * 2048 + tid;
        uint32_t sp = (uint32_t)__cvta_generic_to_shared(
            (float4*)tile + (tid >> 5) * 33 + lane);
        #pragma unroll
        for (int k = 0; k < 8; k++) {
            asm volatile("cp.async.cg.shared.global [%0], [%1], 16;"
                         :: "r"(sp + k * (8 * 33 * 16)), "l"(g + k * NT));
        }
        asm volatile("cp.async.commit_group;");
        asm volatile("cp.async.wait_group 0;" ::: "memory");
    }
    __syncthreads();

    // ---- P2: local scans (threads 0..127 cols, 128..255 rows)
    if (tid < 128) {
        // 1 thread per column, 64 rows, 4 interleaved accumulators
        const float* base = tile + tid;
        Top3 t0 = T3INIT, t1 = T3INIT, t2 = T3INIT, t3 = T3INIT;
        #pragma unroll
        for (int j = 0; j < 16; j++) {
            ins3(t0, base[(4 * j + 0) * 132]);
            ins3(t1, base[(4 * j + 1) * 132]);
            ins3(t2, base[(4 * j + 2) * 132]);
            ins3(t3, base[(4 * j + 3) * 132]);
        }
        merge(t0, t1);
        merge(t2, t3);
        merge(t0, t2);
        cp1[tid] = t0.v1;
        cp2[tid] = t0.v2;
        cp3[tid] = t0.v3;
    } else {
        // 2 threads per row (64 rows), LDS.128; half1 f4 20..31 then 16..19
        const int u  = tid - 128;
        const int r  = u >> 1;
        const int hf = u & 1;
        Top3 t0 = T3INIT, t1 = T3INIT, t2 = T3INIT, t3 = T3INIT;
        const float4* ra = (const float4*)tile + r * 33 + (hf ? 20 : 0);
        #pragma unroll
        for (int j = 0; j < 12; j++) {
            float4 v = ra[j];
            ins3(t0, v.x);
            ins3(t1, v.y);
            ins3(t2, v.z);
            ins3(t3, v.w);
        }
        const float4* rb = (const float4*)tile + r * 33 + (hf ? 16 : 12);
        #pragma unroll
        for (int j = 0; j < 4; j++) {
            float4 v = rb[j];
            ins3(t0, v.x);
            ins3(t1, v.y);
            ins3(t2, v.z);
            ins3(t3, v.w);
        }
        merge(t0, t1);
        merge(t2, t3);
        merge(t0, t2);
        merge_xor1(t0);
        if (!hf) rowInfo[r].x = t0.v3;
    }
    __syncthreads();

    // ---- Exchange col partials with cluster peer, merge
    asm volatile("barrier.cluster.arrive.aligned;" ::: "memory");
    asm volatile("barrier.cluster.wait.aligned;" ::: "memory");

    if (tid < 128) {
        Top3 t;
        t.v1 = cp1[tid];
        t.v2 = cp2[tid];
        t.v3 = cp3[tid];
        uint32_t a1 = (uint32_t)__cvta_generic_to_shared(cp1 + tid);
        uint32_t a2 = (uint32_t)__cvta_generic_to_shared(cp2 + tid);
        uint32_t a3 = (uint32_t)__cvta_generic_to_shared(cp3 + tid);
        ins3(t, ld_peer_f32(a1, peer));
        ins3(t, ld_peer_f32(a2, peer));
        ins3(t, ld_peer_f32(a3, peer));
        colT[tid] = t.v3;
    }
    __syncthreads();
    // done touching peer smem after this point; arrive now, wait at kernel end
    asm volatile("barrier.cluster.arrive.aligned;" ::: "memory");

    // ---- P3: dense output for my 64 rows; __stcs streaming stores
    const float scale = 0.5f * __ldg(ncs + p);
    const float4 cT = *(const float4*)(colT + 4 * lane);
    const uint4 smv = srcm4[p * 32 + lane];
    const float m0 = (smv.x != 0u) ? 1.f : 0.f;
    const float m1 = (smv.y != 0u) ? 1.f : 0.f;
    const float m2 = (smv.z != 0u) ? 1.f : 0.f;
    const float m3 = (smv.w != 0u) ? 1.f : 0.f;

    const float4* tp  = (const float4*)tile + (tid >> 5) * 33 + lane;
    const float2* rip = rowInfo + (tid >> 5);
    float4* sco = out4 + (size_t)p * 4096 + half * 2048 + tid;
    float4* cor = sco + (size_t)PP * 4096;

    if (write_corr) {
        #pragma unroll
        for (int k = 0; k < 8; k++) {
            float2 ri = rip[8 * k];             // warp-uniform (rowTx, refmaskF)
            float4 x  = tp[k * 8 * 33];

            bool ax = x.x >= ri.x, bx = x.x >= cT.x;
            bool ay = x.y >= ri.x, by = x.y >= cT.y;
            bool az = x.z >= ri.x, bz = x.z >= cT.z;
            bool aw = x.w >= ri.x, bw = x.w >= cT.w;

            float svx = scale * __expf(x.x), svy = scale * __expf(x.y);
            float svz = scale * __expf(x.z), svw = scale * __expf(x.w);

            float4 s4;
            s4.x = (ax ? svx : 0.f) + (bx ? svx : 0.f);
            s4.y = (ay ? svy : 0.f) + (by ? svy : 0.f);
            s4.z = (az ? svz : 0.f) + (bz ? svz : 0.f);
            s4.w = (aw ? svw : 0.f) + (bw ? svw : 0.f);
            __stcs(sco + k * NT, s4);

            float4 c4;
            c4.x = ((ax || bx) && x.x > XTHRESH) ? ri.y * m0 : 0.f;
            c4.y = ((ay || by) && x.y > XTHRESH) ? ri.y * m1 : 0.f;
            c4.z = ((az || bz) && x.z > XTHRESH) ? ri.y * m2 : 0.f;
            c4.w = ((aw || bw) && x.w > XTHRESH) ? ri.y * m3 : 0.f;
            __stcs(cor + k * NT, c4);
        }
    } else {
        #pragma unroll
        for (int k = 0; k < 8; k++) {
            float2 ri = rip[8 * k];
            float4 x  = tp[k * 8 * 33];
            bool ax = x.x >= ri.x, bx = x.x >= cT.x;
            bool ay = x.y >= ri.x, by = x.y >= cT.y;
            bool az = x.z >= ri.x, bz = x.z >= cT.z;
            bool aw = x.w >= ri.x, bw = x.w >= cT.w;
            float svx = scale * __expf(x.x), svy = scale * __expf(x.y);
            float svz = scale * __expf(x.z), svw = scale * __expf(x.w);
            float4 s4;
            s4.x = (ax ? svx : 0.f) + (bx ? svx : 0.f);
            s4.y = (ay ? svy : 0.f) + (by ? svy : 0.f);
            s4.z = (az ? svz : 0.f) + (bz ? svz : 0.f);
            s4.w = (aw ? svw : 0.f) + (bw ? svw : 0.f);
            __stcs(sco + k * NT, s4);
        }
    }

    // don't exit while peer may still read my cp arrays
    asm volatile("barrier.cluster.wait.aligned;" ::: "memory");
}

extern "C" void kernel_launch(void* const* d_in, const int* in_sizes, int n_in,
                              void* d_out, int out_size) {
    const float4* msm4       = (const float4*)d_in[0];
    const unsigned int* refm = (const unsigned int*)d_in[1];
    const uint4* srcm4       = (const uint4*)d_in[2];
    const float* ncs         = (const float*)d_in[3];
    float4* out4             = (float4*)d_out;

    const int prs = PP * 128 * 128;
    int write_corr = (out_size >= 2 * prs) ? 1 : 0;

    fine_matching_kernel<<<2 * PP, NT>>>(msm4, refm, srcm4, ncs, out4,
                                         write_corr);
}